// round 1
// baseline (speedup 1.0000x reference)
#include <cuda_runtime.h>
#include <cstdint>

#define Nn 100000
#define Ee 1600000
#define Dd 128

// ---- scratch (device globals: allocation-free rule) ----
__device__ float g_deg[Nn];
__device__ float g_dis[Nn];
__device__ float g_Tx1[(size_t)Nn * Dd];   // 51.2 MB
__device__ float g_Tx2[(size_t)Nn * Dd];   // 51.2 MB

__device__ __forceinline__ void red_add_v4(float* addr, float a, float b, float c, float d) {
    asm volatile("red.global.add.v4.f32 [%0], {%1,%2,%3,%4};"
                 :: "l"(addr), "f"(a), "f"(b), "f"(c), "f"(d) : "memory");
}

// ---- setup kernels ----
__global__ void k_zero_deg() {
    int i = blockIdx.x * blockDim.x + threadIdx.x;
    if (i < Nn) g_deg[i] = 0.f;
}

__global__ void k_deg(const int* __restrict__ ei) {
    int e = blockIdx.x * blockDim.x + threadIdx.x;
    if (e < Ee) {
        int s = ei[e];
        int d = ei[Ee + e];
        if (s != d) atomicAdd(&g_deg[s], 1.f);
    }
}

__global__ void k_dis() {
    int i = blockIdx.x * blockDim.x + threadIdx.x;
    if (i < Nn) {
        float dg = g_deg[i];
        g_dis[i] = (dg > 0.f) ? rsqrtf(dg) : 0.f;
    }
}

// Tx1 = 0 ; Tx2 = -x   (float4 over N*D)
__global__ void k_init(const float* __restrict__ x) {
    int i = blockIdx.x * blockDim.x + threadIdx.x;
    if (i < (Nn * Dd) / 4) {
        ((float4*)g_Tx1)[i] = make_float4(0.f, 0.f, 0.f, 0.f);
        float4 xv = ((const float4*)x)[i];
        ((float4*)g_Tx2)[i] = make_float4(-xv.x, -xv.y, -xv.z, -xv.w);
    }
}

// ---- SPMM: out[dst] += scale * w_e * feat[src], one warp per edge ----
__global__ void k_spmm(const int* __restrict__ ei, const float* __restrict__ feat,
                       float* __restrict__ out, float scale) {
    int warp = (blockIdx.x * blockDim.x + threadIdx.x) >> 5;
    int lane = threadIdx.x & 31;
    if (warp >= Ee) return;
    int s = __ldg(&ei[warp]);
    int d = __ldg(&ei[Ee + warp]);
    if (s == d) return;
    float w = -scale * g_dis[s] * g_dis[d];
    if (w == 0.f) return;
    float4 v = ((const float4*)(feat + (size_t)s * Dd))[lane];
    float* ap = out + (size_t)d * Dd + lane * 4;
    red_add_v4(ap, w * v.x, w * v.y, w * v.z, w * v.w);
}

// ---- GEMM: out[N,128] = [x|Tx1|Tx2](N,384) @ W(384,128) + bias ----
// CTA: 64 rows x 128 cols, 128 threads, 8x8 micro-tile per thread, BK=16
#define BM 64
#define BK 16

__global__ void k_gemm(const float* __restrict__ x, const float* __restrict__ W,
                       const float* __restrict__ bias, float* __restrict__ out) {
    __shared__ float As[BK][BM];   // transposed A tile
    __shared__ float Bs[BK][Dd];

    int t  = threadIdx.x;
    int tx = t & 15;   // col group: cols tx*8 .. tx*8+7
    int ty = t >> 4;   // row group: rows ty*8 .. ty*8+7
    int row0 = blockIdx.x * BM;

    float acc[8][8];
    #pragma unroll
    for (int i = 0; i < 8; i++)
        #pragma unroll
        for (int j = 0; j < 8; j++) acc[i][j] = 0.f;

    for (int kt = 0; kt < 24; kt++) {
        int sel = kt >> 3;                          // 0:x 1:Tx1 2:Tx2
        const float* A = (sel == 0) ? x : (sel == 1) ? g_Tx1 : g_Tx2;
        int kl0 = (kt & 7) * BK;

        // load A tile: 64 rows x 16 k = 256 float4 -> 2 per thread
        #pragma unroll
        for (int i = 0; i < 2; i++) {
            int idx = t + i * 128;
            int r   = idx >> 2;       // 0..63
            int kq  = idx & 3;        // 0..3 (float4 within the 16-wide k slab)
            int grow = row0 + r;
            float4 v = make_float4(0.f, 0.f, 0.f, 0.f);
            if (grow < Nn)
                v = *(const float4*)(A + (size_t)grow * Dd + kl0 + kq * 4);
            As[kq * 4 + 0][r] = v.x;
            As[kq * 4 + 1][r] = v.y;
            As[kq * 4 + 2][r] = v.z;
            As[kq * 4 + 3][r] = v.w;
        }
        // load B tile: 16 rows x 128 cols = 512 float4 -> 4 per thread
        const float* Bt = W + (size_t)(kt * BK) * Dd;
        #pragma unroll
        for (int i = 0; i < 4; i++) {
            int idx = t + i * 128;    // float4 index 0..511
            int r   = idx >> 5;       // 0..15
            int c   = (idx & 31) * 4;
            *(float4*)&Bs[r][c] = *(const float4*)(Bt + r * Dd + c);
        }
        __syncthreads();

        #pragma unroll
        for (int kk = 0; kk < BK; kk++) {
            float a[8], b[8];
            #pragma unroll
            for (int i = 0; i < 8; i++) a[i] = As[kk][ty * 8 + i];
            #pragma unroll
            for (int j = 0; j < 8; j++) b[j] = Bs[kk][tx * 8 + j];
            #pragma unroll
            for (int i = 0; i < 8; i++)
                #pragma unroll
                for (int j = 0; j < 8; j++)
                    acc[i][j] += a[i] * b[j];
        }
        __syncthreads();
    }

    // epilogue: + bias, store
    #pragma unroll
    for (int i = 0; i < 8; i++) {
        int grow = row0 + ty * 8 + i;
        if (grow < Nn) {
            #pragma unroll
            for (int j = 0; j < 8; j += 4) {
                int c = tx * 8 + j;
                float4 o = make_float4(acc[i][j + 0] + bias[c + 0],
                                       acc[i][j + 1] + bias[c + 1],
                                       acc[i][j + 2] + bias[c + 2],
                                       acc[i][j + 3] + bias[c + 3]);
                *(float4*)(out + (size_t)grow * Dd + c) = o;
            }
        }
    }
}

extern "C" void kernel_launch(void* const* d_in, const int* in_sizes, int n_in,
                              void* d_out, int out_size) {
    const float* x    = (const float*)d_in[0];
    const int*   ei   = (const int*)d_in[1];
    const float* W    = (const float*)d_in[2];   // [3,128,128] == [384,128]
    const float* bias = (const float*)d_in[3];
    float* out = (float*)d_out;

    (void)in_sizes; (void)n_in; (void)out_size;

    float* Tx1; cudaGetSymbolAddress((void**)&Tx1, g_Tx1);
    float* Tx2; cudaGetSymbolAddress((void**)&Tx2, g_Tx2);

    // degree + normalization
    k_zero_deg<<<(Nn + 255) / 256, 256>>>();
    k_deg<<<(Ee + 255) / 256, 256>>>(ei);
    k_dis<<<(Nn + 255) / 256, 256>>>();

    // Tx1 = 0, Tx2 = -x
    k_init<<<(Nn * Dd / 4 + 255) / 256, 256>>>(x);

    // Tx1 = spmm(x)       : Tx1[d] += -dis[s]dis[d] * x[s]
    k_spmm<<<Ee / 8, 256>>>(ei, x, Tx1, 1.0f);
    // Tx2 = 2*spmm(Tx1)-x : Tx2[d] += -2*dis[s]dis[d] * Tx1[s]   (Tx2 pre-init to -x)
    k_spmm<<<Ee / 8, 256>>>(ei, Tx1, Tx2, 2.0f);

    // out = x@W0 + Tx1@W1 + Tx2@W2 + bias
    k_gemm<<<(Nn + BM - 1) / BM, 128>>>(x, W, bias, out);
}

// round 2
// speedup vs baseline: 1.6168x; 1.6168x over previous
#include <cuda_runtime.h>
#include <cstdint>

#define Nn 100000
#define Ee 1600000
#define Dd 128

// ---- scratch (device globals: allocation-free rule) ----
__device__ int   g_deg[Nn];
__device__ int   g_cnt[Nn];
__device__ float g_dis[Nn];
__device__ int   g_rowptr[Nn + 1];
__device__ int   g_cursor[Nn];
__device__ int   g_csr_src[Ee];
__device__ float g_csr_w[Ee];
__device__ float g_Tx1[(size_t)Nn * Dd];
__device__ float g_Tx2[(size_t)Nn * Dd];

// ============================ setup ============================
__global__ void k_zero() {
    int i = blockIdx.x * blockDim.x + threadIdx.x;
    if (i < Nn) { g_deg[i] = 0; g_cnt[i] = 0; }
}

__global__ void k_count(const int* __restrict__ ei) {
    int e = blockIdx.x * blockDim.x + threadIdx.x;
    if (e < Ee) {
        int s = ei[e];
        int d = ei[Ee + e];
        if (s != d) {
            atomicAdd(&g_deg[s], 1);
            atomicAdd(&g_cnt[d], 1);
        }
    }
}

__global__ void k_dis() {
    int i = blockIdx.x * blockDim.x + threadIdx.x;
    if (i < Nn) {
        int dg = g_deg[i];
        g_dis[i] = (dg > 0) ? rsqrtf((float)dg) : 0.f;
    }
}

// single-block exclusive scan of g_cnt -> g_rowptr (+ copy to cursor)
__global__ void k_scan() {
    __shared__ int sh[1024];
    const int C = (Nn + 1023) / 1024;   // 98
    int t = threadIdx.x;
    int base = t * C;
    int s = 0;
    for (int i = 0; i < C; i++) {
        int idx = base + i;
        if (idx < Nn) s += g_cnt[idx];
    }
    sh[t] = s;
    __syncthreads();
    for (int off = 1; off < 1024; off <<= 1) {
        int v = 0;
        if (t >= off) v = sh[t - off];
        __syncthreads();
        sh[t] += v;
        __syncthreads();
    }
    if (t == 1023) g_rowptr[Nn] = sh[1023];
    int run = sh[t] - s;   // exclusive prefix
    for (int i = 0; i < C; i++) {
        int idx = base + i;
        if (idx < Nn) {
            g_rowptr[idx] = run;
            g_cursor[idx] = run;
            run += g_cnt[idx];
        }
    }
}

__global__ void k_fill(const int* __restrict__ ei) {
    int e = blockIdx.x * blockDim.x + threadIdx.x;
    if (e < Ee) {
        int s = ei[e];
        int d = ei[Ee + e];
        if (s != d) {
            float w = g_dis[s] * g_dis[d];
            int p = atomicAdd(&g_cursor[d], 1);
            g_csr_src[p] = s;
            g_csr_w[p] = w;
        }
    }
}

// ================= CSR SPMM: out[r] = alpha*Sum_j w_j feat[src_j] + beta*xin[r] ==========
__global__ void k_spmm_csr(const float* __restrict__ feat, const float* __restrict__ xin,
                           float* __restrict__ out, float alpha, float beta) {
    int w = (blockIdx.x * blockDim.x + threadIdx.x) >> 5;
    int lane = threadIdx.x & 31;
    if (w >= Nn) return;
    int start = g_rowptr[w];
    int end   = g_rowptr[w + 1];
    float4 acc = make_float4(0.f, 0.f, 0.f, 0.f);
    const float4* f4 = (const float4*)feat;

    for (int base = start; base < end; base += 32) {
        int j = base + lane;
        int   sj = (j < end) ? g_csr_src[j] : 0;
        float wj = (j < end) ? g_csr_w[j] : 0.f;
        int m = end - base; if (m > 32) m = 32;
        int k = 0;
        for (; k + 4 <= m; k += 4) {
            int   s0 = __shfl_sync(~0u, sj, k + 0);
            int   s1 = __shfl_sync(~0u, sj, k + 1);
            int   s2 = __shfl_sync(~0u, sj, k + 2);
            int   s3 = __shfl_sync(~0u, sj, k + 3);
            float w0 = __shfl_sync(~0u, wj, k + 0);
            float w1 = __shfl_sync(~0u, wj, k + 1);
            float w2 = __shfl_sync(~0u, wj, k + 2);
            float w3 = __shfl_sync(~0u, wj, k + 3);
            float4 v0 = f4[(size_t)s0 * 32 + lane];
            float4 v1 = f4[(size_t)s1 * 32 + lane];
            float4 v2 = f4[(size_t)s2 * 32 + lane];
            float4 v3 = f4[(size_t)s3 * 32 + lane];
            acc.x += w0 * v0.x; acc.y += w0 * v0.y; acc.z += w0 * v0.z; acc.w += w0 * v0.w;
            acc.x += w1 * v1.x; acc.y += w1 * v1.y; acc.z += w1 * v1.z; acc.w += w1 * v1.w;
            acc.x += w2 * v2.x; acc.y += w2 * v2.y; acc.z += w2 * v2.z; acc.w += w2 * v2.w;
            acc.x += w3 * v3.x; acc.y += w3 * v3.y; acc.z += w3 * v3.z; acc.w += w3 * v3.w;
        }
        for (; k < m; k++) {
            int   s0 = __shfl_sync(~0u, sj, k);
            float w0 = __shfl_sync(~0u, wj, k);
            float4 v0 = f4[(size_t)s0 * 32 + lane];
            acc.x += w0 * v0.x; acc.y += w0 * v0.y; acc.z += w0 * v0.z; acc.w += w0 * v0.w;
        }
    }
    size_t o = (size_t)w * 32 + lane;
    float4 r;
    if (beta != 0.f) {
        float4 xv = ((const float4*)xin)[o];
        r.x = alpha * acc.x + beta * xv.x;
        r.y = alpha * acc.y + beta * xv.y;
        r.z = alpha * acc.z + beta * xv.z;
        r.w = alpha * acc.w + beta * xv.w;
    } else {
        r.x = alpha * acc.x; r.y = alpha * acc.y;
        r.z = alpha * acc.z; r.w = alpha * acc.w;
    }
    ((float4*)out)[o] = r;
}

// ================= TF32 tensor-core GEMM =================
// out[N,128] = [x|Tx1|Tx2](N,384) @ W(384,128) + bias
// CTA: 256 thr = 8 warps, tile 128M x 128N, K chunks of 32.
// warp tile: 32M x 64N via m16n8k8 (2 M-tiles x 8 N-tiles)

__device__ __forceinline__ uint32_t f2tf32(float f) {
    uint32_t r;
    asm("cvt.rna.tf32.f32 %0, %1;" : "=r"(r) : "f"(f));
    return r;
}

__device__ __forceinline__ void mma_tf32(float& d0, float& d1, float& d2, float& d3,
                                         uint32_t a0, uint32_t a1, uint32_t a2, uint32_t a3,
                                         uint32_t b0, uint32_t b1) {
    asm volatile("mma.sync.aligned.m16n8k8.row.col.f32.tf32.tf32.f32 "
                 "{%0,%1,%2,%3}, {%4,%5,%6,%7}, {%8,%9}, {%0,%1,%2,%3};\n"
                 : "+f"(d0), "+f"(d1), "+f"(d2), "+f"(d3)
                 : "r"(a0), "r"(a1), "r"(a2), "r"(a3), "r"(b0), "r"(b1));
}

#define AST 36
#define BST 136

__global__ void __launch_bounds__(256, 2)
k_gemm(const float* __restrict__ x, const float* __restrict__ W,
       const float* __restrict__ bias, float* __restrict__ out) {
    __shared__ uint32_t As[128 * AST];
    __shared__ uint32_t Bs[32 * BST];

    int t = threadIdx.x;
    int lane = t & 31;
    int wid = t >> 5;
    int wm = (wid & 3) * 32;   // warp M offset
    int wn = (wid >> 2) * 64;  // warp N offset
    int row0 = blockIdx.x * 128;

    float acc[2][8][4];
    #pragma unroll
    for (int mi = 0; mi < 2; mi++)
        #pragma unroll
        for (int ni = 0; ni < 8; ni++)
            #pragma unroll
            for (int q = 0; q < 4; q++) acc[mi][ni][q] = 0.f;

    for (int chunk = 0; chunk < 12; chunk++) {
        int sel = chunk >> 2;
        const float* A = (sel == 0) ? x : (sel == 1) ? g_Tx1 : g_Tx2;
        int kl0 = (chunk & 3) * 32;

        // load A tile 128x32 (1024 float4, 4 per thread)
        #pragma unroll
        for (int i = 0; i < 4; i++) {
            int idx = t + i * 256;
            int r = idx >> 3;
            int c = (idx & 7) * 4;
            int grow = row0 + r;
            float4 v = make_float4(0.f, 0.f, 0.f, 0.f);
            if (grow < Nn) v = *(const float4*)(A + (size_t)grow * Dd + kl0 + c);
            uint32_t* p = &As[r * AST + c];
            p[0] = f2tf32(v.x); p[1] = f2tf32(v.y); p[2] = f2tf32(v.z); p[3] = f2tf32(v.w);
        }
        // load B tile 32x128 (1024 float4... 1024 floats*4 = 4096 floats = 1024 f4/4 -> 256 f4? no: 4096 floats = 1024 float4, 4 per thread)
        const float* Bt = W + (size_t)(chunk * 32) * Dd;
        #pragma unroll
        for (int i = 0; i < 4; i++) {
            int idx = t + i * 256;
            int r = idx >> 5;          // 0..31
            int c = (idx & 31) * 4;    // 0..124
            float4 v = *(const float4*)(Bt + r * Dd + c);
            uint32_t* p = &Bs[r * BST + c];
            p[0] = f2tf32(v.x); p[1] = f2tf32(v.y); p[2] = f2tf32(v.z); p[3] = f2tf32(v.w);
        }
        __syncthreads();

        #pragma unroll
        for (int ks = 0; ks < 4; ks++) {
            int ar = wm + (lane >> 2);
            int ac = ks * 8 + (lane & 3);
            uint32_t a[2][4];
            #pragma unroll
            for (int mi = 0; mi < 2; mi++) {
                a[mi][0] = As[(ar + mi * 16 + 0) * AST + ac + 0];
                a[mi][1] = As[(ar + mi * 16 + 8) * AST + ac + 0];
                a[mi][2] = As[(ar + mi * 16 + 0) * AST + ac + 4];
                a[mi][3] = As[(ar + mi * 16 + 8) * AST + ac + 4];
            }
            int br = ks * 8 + (lane & 3);
            int bc = wn + (lane >> 2);
            uint32_t b[8][2];
            #pragma unroll
            for (int ni = 0; ni < 8; ni++) {
                b[ni][0] = Bs[(br + 0) * BST + bc + ni * 8];
                b[ni][1] = Bs[(br + 4) * BST + bc + ni * 8];
            }
            #pragma unroll
            for (int mi = 0; mi < 2; mi++)
                #pragma unroll
                for (int ni = 0; ni < 8; ni++)
                    mma_tf32(acc[mi][ni][0], acc[mi][ni][1], acc[mi][ni][2], acc[mi][ni][3],
                             a[mi][0], a[mi][1], a[mi][2], a[mi][3],
                             b[ni][0], b[ni][1]);
        }
        __syncthreads();
    }

    // epilogue: + bias, store float2 pairs
    #pragma unroll
    for (int mi = 0; mi < 2; mi++) {
        int r0 = row0 + wm + mi * 16 + (lane >> 2);
        #pragma unroll
        for (int ni = 0; ni < 8; ni++) {
            int c = wn + ni * 8 + (lane & 3) * 2;
            float b0 = __ldg(&bias[c]);
            float b1 = __ldg(&bias[c + 1]);
            if (r0 < Nn) {
                float2 o = make_float2(acc[mi][ni][0] + b0, acc[mi][ni][1] + b1);
                *(float2*)(out + (size_t)r0 * Dd + c) = o;
            }
            if (r0 + 8 < Nn) {
                float2 o = make_float2(acc[mi][ni][2] + b0, acc[mi][ni][3] + b1);
                *(float2*)(out + (size_t)(r0 + 8) * Dd + c) = o;
            }
        }
    }
}

extern "C" void kernel_launch(void* const* d_in, const int* in_sizes, int n_in,
                              void* d_out, int out_size) {
    const float* x    = (const float*)d_in[0];
    const int*   ei   = (const int*)d_in[1];
    const float* W    = (const float*)d_in[2];   // [3,128,128] == [384,128]
    const float* bias = (const float*)d_in[3];
    float* out = (float*)d_out;
    (void)in_sizes; (void)n_in; (void)out_size;

    float* Tx1; cudaGetSymbolAddress((void**)&Tx1, g_Tx1);
    float* Tx2; cudaGetSymbolAddress((void**)&Tx2, g_Tx2);

    k_zero <<<(Nn + 255) / 256, 256>>>();
    k_count<<<(Ee + 255) / 256, 256>>>(ei);
    k_dis  <<<(Nn + 255) / 256, 256>>>();
    k_scan <<<1, 1024>>>();
    k_fill <<<(Ee + 255) / 256, 256>>>(ei);

    // Tx1 = spmm(x) = -(sum w x[s])
    k_spmm_csr<<<(Nn * 32 + 255) / 256, 256>>>(x, x, Tx1, -1.0f, 0.0f);
    // Tx2 = 2*spmm(Tx1) - x = -2*(sum w Tx1[s]) - x
    k_spmm_csr<<<(Nn * 32 + 255) / 256, 256>>>(Tx1, x, Tx2, -2.0f, -1.0f);

    // out = x@W0 + Tx1@W1 + Tx2@W2 + bias  (tf32 tensor cores)
    k_gemm<<<(Nn + 127) / 128, 256>>>(x, W, bias, out);
}

// round 3
// speedup vs baseline: 2.4205x; 1.4971x over previous
#include <cuda_runtime.h>
#include <cstdint>

#define Nn 100000
#define Ee 1600000
#define Dd 128
#define SCAN_BLOCKS ((Nn + 1023) / 1024)   // 98

// ---- scratch (device globals: allocation-free rule) ----
__device__ int   g_deg[Nn];
__device__ int   g_cnt[Nn];
__device__ float g_dis[Nn];
__device__ int   g_rowptr[Nn + 1];
__device__ int   g_cursor[Nn];
__device__ int   g_bsum[SCAN_BLOCKS];
__device__ int   g_boff[SCAN_BLOCKS + 1];
__device__ int   g_csr_src[Ee];
__device__ float g_csr_w[Ee];
__device__ float g_Tx1[(size_t)Nn * Dd];
__device__ float g_Tx2[(size_t)Nn * Dd];

// ============================ setup ============================
__global__ void k_zero() {
    int i = blockIdx.x * blockDim.x + threadIdx.x;
    if (i < Nn) { g_deg[i] = 0; g_cnt[i] = 0; }
}

__global__ void k_count(const int* __restrict__ ei) {
    int e = blockIdx.x * blockDim.x + threadIdx.x;
    if (e < Ee) {
        int s = ei[e];
        int d = ei[Ee + e];
        if (s != d) {
            atomicAdd(&g_deg[s], 1);
            atomicAdd(&g_cnt[d], 1);
        }
    }
}

__global__ void k_dis() {
    int i = blockIdx.x * blockDim.x + threadIdx.x;
    if (i < Nn) {
        int dg = g_deg[i];
        g_dis[i] = (dg > 0) ? rsqrtf((float)dg) : 0.f;
    }
}

// ---- 3-phase device-wide exclusive scan of g_cnt -> g_rowptr / g_cursor ----
__global__ void k_scan1() {
    __shared__ int sh[1024];
    int t = threadIdx.x;
    int i = blockIdx.x * 1024 + t;
    int v = (i < Nn) ? g_cnt[i] : 0;
    sh[t] = v;
    __syncthreads();
    #pragma unroll
    for (int off = 1; off < 1024; off <<= 1) {
        int u = (t >= off) ? sh[t - off] : 0;
        __syncthreads();
        sh[t] += u;
        __syncthreads();
    }
    if (i < Nn) g_rowptr[i] = sh[t] - v;          // block-local exclusive prefix
    if (t == 1023) g_bsum[blockIdx.x] = sh[1023]; // block total
}

__global__ void k_scan2() {
    __shared__ int sh[SCAN_BLOCKS];
    int t = threadIdx.x;   // 128 threads
    if (t == 0) {
        int run = 0;
        for (int b = 0; b < SCAN_BLOCKS; b++) { sh[b] = run; run += g_bsum[b]; }
        g_boff[SCAN_BLOCKS] = run;
        g_rowptr[Nn] = run;
    }
    __syncthreads();
    for (int b = t; b < SCAN_BLOCKS; b += 128) g_boff[b] = sh[b];
}

__global__ void k_scan3() {
    int i = blockIdx.x * 1024 + threadIdx.x;
    if (i < Nn) {
        int r = g_rowptr[i] + g_boff[blockIdx.x];
        g_rowptr[i] = r;
        g_cursor[i] = r;
    }
}

__global__ void k_fill(const int* __restrict__ ei) {
    int e = blockIdx.x * blockDim.x + threadIdx.x;
    if (e < Ee) {
        int s = ei[e];
        int d = ei[Ee + e];
        if (s != d) {
            float w = g_dis[s] * g_dis[d];
            int p = atomicAdd(&g_cursor[d], 1);
            g_csr_src[p] = s;
            g_csr_w[p] = w;
        }
    }
}

// ================= CSR SPMM: out[r] = alpha*Sum_j w_j feat[src_j] + beta*xin[r] ==========
__global__ void k_spmm_csr(const float* __restrict__ feat, const float* __restrict__ xin,
                           float* __restrict__ out, float alpha, float beta) {
    int w = (blockIdx.x * blockDim.x + threadIdx.x) >> 5;
    int lane = threadIdx.x & 31;
    if (w >= Nn) return;
    int start = g_rowptr[w];
    int end   = g_rowptr[w + 1];
    float4 acc = make_float4(0.f, 0.f, 0.f, 0.f);
    const float4* f4 = (const float4*)feat;

    for (int base = start; base < end; base += 32) {
        int j = base + lane;
        int   sj = (j < end) ? g_csr_src[j] : 0;
        float wj = (j < end) ? g_csr_w[j] : 0.f;
        int m = end - base; if (m > 32) m = 32;
        int k = 0;
        for (; k + 4 <= m; k += 4) {
            int   s0 = __shfl_sync(~0u, sj, k + 0);
            int   s1 = __shfl_sync(~0u, sj, k + 1);
            int   s2 = __shfl_sync(~0u, sj, k + 2);
            int   s3 = __shfl_sync(~0u, sj, k + 3);
            float w0 = __shfl_sync(~0u, wj, k + 0);
            float w1 = __shfl_sync(~0u, wj, k + 1);
            float w2 = __shfl_sync(~0u, wj, k + 2);
            float w3 = __shfl_sync(~0u, wj, k + 3);
            float4 v0 = f4[(size_t)s0 * 32 + lane];
            float4 v1 = f4[(size_t)s1 * 32 + lane];
            float4 v2 = f4[(size_t)s2 * 32 + lane];
            float4 v3 = f4[(size_t)s3 * 32 + lane];
            acc.x += w0 * v0.x; acc.y += w0 * v0.y; acc.z += w0 * v0.z; acc.w += w0 * v0.w;
            acc.x += w1 * v1.x; acc.y += w1 * v1.y; acc.z += w1 * v1.z; acc.w += w1 * v1.w;
            acc.x += w2 * v2.x; acc.y += w2 * v2.y; acc.z += w2 * v2.z; acc.w += w2 * v2.w;
            acc.x += w3 * v3.x; acc.y += w3 * v3.y; acc.z += w3 * v3.z; acc.w += w3 * v3.w;
        }
        for (; k < m; k++) {
            int   s0 = __shfl_sync(~0u, sj, k);
            float w0 = __shfl_sync(~0u, wj, k);
            float4 v0 = f4[(size_t)s0 * 32 + lane];
            acc.x += w0 * v0.x; acc.y += w0 * v0.y; acc.z += w0 * v0.z; acc.w += w0 * v0.w;
        }
    }
    size_t o = (size_t)w * 32 + lane;
    float4 r;
    if (beta != 0.f) {
        float4 xv = ((const float4*)xin)[o];
        r.x = alpha * acc.x + beta * xv.x;
        r.y = alpha * acc.y + beta * xv.y;
        r.z = alpha * acc.z + beta * xv.z;
        r.w = alpha * acc.w + beta * xv.w;
    } else {
        r.x = alpha * acc.x; r.y = alpha * acc.y;
        r.z = alpha * acc.z; r.w = alpha * acc.w;
    }
    ((float4*)out)[o] = r;
}

// ================= TF32 tensor-core GEMM =================
__device__ __forceinline__ uint32_t f2tf32(float f) {
    uint32_t r;
    asm("cvt.rna.tf32.f32 %0, %1;" : "=r"(r) : "f"(f));
    return r;
}

__device__ __forceinline__ void mma_tf32(float& d0, float& d1, float& d2, float& d3,
                                         uint32_t a0, uint32_t a1, uint32_t a2, uint32_t a3,
                                         uint32_t b0, uint32_t b1) {
    asm volatile("mma.sync.aligned.m16n8k8.row.col.f32.tf32.tf32.f32 "
                 "{%0,%1,%2,%3}, {%4,%5,%6,%7}, {%8,%9}, {%0,%1,%2,%3};\n"
                 : "+f"(d0), "+f"(d1), "+f"(d2), "+f"(d3)
                 : "r"(a0), "r"(a1), "r"(a2), "r"(a3), "r"(b0), "r"(b1));
}

#define AST 36
#define BST 136

__global__ void __launch_bounds__(256, 2)
k_gemm(const float* __restrict__ x, const float* __restrict__ W,
       const float* __restrict__ bias, float* __restrict__ out) {
    __shared__ uint32_t As[128 * AST];
    __shared__ uint32_t Bs[32 * BST];

    int t = threadIdx.x;
    int lane = t & 31;
    int wid = t >> 5;
    int wm = (wid & 3) * 32;
    int wn = (wid >> 2) * 64;
    int row0 = blockIdx.x * 128;

    float acc[2][8][4];
    #pragma unroll
    for (int mi = 0; mi < 2; mi++)
        #pragma unroll
        for (int ni = 0; ni < 8; ni++)
            #pragma unroll
            for (int q = 0; q < 4; q++) acc[mi][ni][q] = 0.f;

    for (int chunk = 0; chunk < 12; chunk++) {
        int sel = chunk >> 2;
        const float* A = (sel == 0) ? x : (sel == 1) ? g_Tx1 : g_Tx2;
        int kl0 = (chunk & 3) * 32;

        #pragma unroll
        for (int i = 0; i < 4; i++) {
            int idx = t + i * 256;
            int r = idx >> 3;
            int c = (idx & 7) * 4;
            int grow = row0 + r;
            float4 v = make_float4(0.f, 0.f, 0.f, 0.f);
            if (grow < Nn) v = *(const float4*)(A + (size_t)grow * Dd + kl0 + c);
            uint32_t* p = &As[r * AST + c];
            p[0] = f2tf32(v.x); p[1] = f2tf32(v.y); p[2] = f2tf32(v.z); p[3] = f2tf32(v.w);
        }
        const float* Bt = W + (size_t)(chunk * 32) * Dd;
        #pragma unroll
        for (int i = 0; i < 4; i++) {
            int idx = t + i * 256;
            int r = idx >> 5;
            int c = (idx & 31) * 4;
            float4 v = *(const float4*)(Bt + r * Dd + c);
            uint32_t* p = &Bs[r * BST + c];
            p[0] = f2tf32(v.x); p[1] = f2tf32(v.y); p[2] = f2tf32(v.z); p[3] = f2tf32(v.w);
        }
        __syncthreads();

        #pragma unroll
        for (int ks = 0; ks < 4; ks++) {
            int ar = wm + (lane >> 2);
            int ac = ks * 8 + (lane & 3);
            uint32_t a[2][4];
            #pragma unroll
            for (int mi = 0; mi < 2; mi++) {
                a[mi][0] = As[(ar + mi * 16 + 0) * AST + ac + 0];
                a[mi][1] = As[(ar + mi * 16 + 8) * AST + ac + 0];
                a[mi][2] = As[(ar + mi * 16 + 0) * AST + ac + 4];
                a[mi][3] = As[(ar + mi * 16 + 8) * AST + ac + 4];
            }
            int br = ks * 8 + (lane & 3);
            int bc = wn + (lane >> 2);
            uint32_t b[8][2];
            #pragma unroll
            for (int ni = 0; ni < 8; ni++) {
                b[ni][0] = Bs[(br + 0) * BST + bc + ni * 8];
                b[ni][1] = Bs[(br + 4) * BST + bc + ni * 8];
            }
            #pragma unroll
            for (int mi = 0; mi < 2; mi++)
                #pragma unroll
                for (int ni = 0; ni < 8; ni++)
                    mma_tf32(acc[mi][ni][0], acc[mi][ni][1], acc[mi][ni][2], acc[mi][ni][3],
                             a[mi][0], a[mi][1], a[mi][2], a[mi][3],
                             b[ni][0], b[ni][1]);
        }
        __syncthreads();
    }

    #pragma unroll
    for (int mi = 0; mi < 2; mi++) {
        int r0 = row0 + wm + mi * 16 + (lane >> 2);
        #pragma unroll
        for (int ni = 0; ni < 8; ni++) {
            int c = wn + ni * 8 + (lane & 3) * 2;
            float b0 = __ldg(&bias[c]);
            float b1 = __ldg(&bias[c + 1]);
            if (r0 < Nn) {
                float2 o = make_float2(acc[mi][ni][0] + b0, acc[mi][ni][1] + b1);
                *(float2*)(out + (size_t)r0 * Dd + c) = o;
            }
            if (r0 + 8 < Nn) {
                float2 o = make_float2(acc[mi][ni][2] + b0, acc[mi][ni][3] + b1);
                *(float2*)(out + (size_t)(r0 + 8) * Dd + c) = o;
            }
        }
    }
}

extern "C" void kernel_launch(void* const* d_in, const int* in_sizes, int n_in,
                              void* d_out, int out_size) {
    const float* x    = (const float*)d_in[0];
    const int*   ei   = (const int*)d_in[1];
    const float* W    = (const float*)d_in[2];
    const float* bias = (const float*)d_in[3];
    float* out = (float*)d_out;
    (void)in_sizes; (void)n_in; (void)out_size;

    float* Tx1; cudaGetSymbolAddress((void**)&Tx1, g_Tx1);
    float* Tx2; cudaGetSymbolAddress((void**)&Tx2, g_Tx2);

    k_zero <<<(Nn + 255) / 256, 256>>>();
    k_count<<<(Ee + 255) / 256, 256>>>(ei);
    k_dis  <<<(Nn + 255) / 256, 256>>>();
    k_scan1<<<SCAN_BLOCKS, 1024>>>();
    k_scan2<<<1, 128>>>();
    k_scan3<<<SCAN_BLOCKS, 1024>>>();
    k_fill <<<(Ee + 255) / 256, 256>>>(ei);

    k_spmm_csr<<<(Nn * 32 + 255) / 256, 256>>>(x, x, Tx1, -1.0f, 0.0f);
    k_spmm_csr<<<(Nn * 32 + 255) / 256, 256>>>(Tx1, x, Tx2, -2.0f, -1.0f);

    k_gemm<<<(Nn + 127) / 128, 256>>>(x, W, bias, out);
}

// round 4
// speedup vs baseline: 2.4404x; 1.0082x over previous
#include <cuda_runtime.h>
#include <cstdint>

#define Nn 100000
#define Ee 1600000
#define Dd 128
#define SCAN_BLOCKS ((Nn + 1023) / 1024)   // 98

// ---- scratch (device globals: allocation-free rule) ----
__device__ int      g_deg[Nn];
__device__ int      g_cnt[Nn];
__device__ float    g_dis[Nn];
__device__ int      g_rowptr[Nn + 1];
__device__ int      g_cursor[Nn];
__device__ int      g_bsum[SCAN_BLOCKS];
__device__ int      g_boff[SCAN_BLOCKS + 1];
__device__ int2     g_csr[Ee];                 // {src, w_bits}
__device__ uint32_t g_Wt[12 * 128 * 32];       // tf32, permuted [chunk][n][kmap]
__device__ float    g_Tx1[(size_t)Nn * Dd];
__device__ float    g_Tx2[(size_t)Nn * Dd];

__device__ __forceinline__ uint32_t f2tf32(float f) {
    uint32_t r;
    asm("cvt.rna.tf32.f32 %0, %1;" : "=r"(r) : "f"(f));
    return r;
}

// ============================ setup ============================
__global__ void k_zero_a() {
    int i = blockIdx.x * blockDim.x + threadIdx.x;
    if (i < Nn / 2) { g_deg[i] = 0; g_cnt[i] = 0; }
}
__global__ void k_zero_b() {
    int i = Nn / 2 + blockIdx.x * blockDim.x + threadIdx.x;
    if (i < Nn) { g_deg[i] = 0; g_cnt[i] = 0; }
}

// W[384,128] fp32 -> g_Wt[chunk][n][p] tf32, p = kmap(kloc)
__global__ void k_wprep(const float* __restrict__ W) {
    int i = blockIdx.x * blockDim.x + threadIdx.x;
    if (i >= 12 * 128 * 32) return;
    int chunk = i >> 12;
    int n     = (i >> 5) & 127;
    int p     = i & 31;
    // inverse kmap: k = (p>>3)*8 + ((p&1)<<2) + ((p&7)>>1)
    int k = ((p >> 3) << 3) + ((p & 1) << 2) + ((p & 7) >> 1);
    int kg = chunk * 32 + k;
    g_Wt[i] = f2tf32(W[kg * Dd + n]);
}

__global__ void k_count(const int* __restrict__ ei) {
    int e = blockIdx.x * blockDim.x + threadIdx.x;
    if (e < Ee) {
        int s = ei[e];
        int d = ei[Ee + e];
        if (s != d) {
            atomicAdd(&g_deg[s], 1);
            atomicAdd(&g_cnt[d], 1);
        }
    }
}

__global__ void k_dis() {
    int i = blockIdx.x * blockDim.x + threadIdx.x;
    if (i < Nn) {
        int dg = g_deg[i];
        g_dis[i] = (dg > 0) ? rsqrtf((float)dg) : 0.f;
    }
}

// ---- 3-phase device-wide exclusive scan of g_cnt -> g_rowptr / g_cursor ----
__global__ void k_scan1() {
    __shared__ int sh[1024];
    int t = threadIdx.x;
    int i = blockIdx.x * 1024 + t;
    int v = (i < Nn) ? g_cnt[i] : 0;
    sh[t] = v;
    __syncthreads();
    #pragma unroll
    for (int off = 1; off < 1024; off <<= 1) {
        int u = (t >= off) ? sh[t - off] : 0;
        __syncthreads();
        sh[t] += u;
        __syncthreads();
    }
    if (i < Nn) g_rowptr[i] = sh[t] - v;
    if (t == 1023) g_bsum[blockIdx.x] = sh[1023];
}

__global__ void k_scan2() {
    __shared__ int sh[SCAN_BLOCKS];
    int t = threadIdx.x;
    if (t == 0) {
        int run = 0;
        for (int b = 0; b < SCAN_BLOCKS; b++) { sh[b] = run; run += g_bsum[b]; }
        g_boff[SCAN_BLOCKS] = run;
        g_rowptr[Nn] = run;
    }
    __syncthreads();
    for (int b = t; b < SCAN_BLOCKS; b += 128) g_boff[b] = sh[b];
}

__global__ void k_scan3() {
    int i = blockIdx.x * 1024 + threadIdx.x;
    if (i < Nn) {
        int r = g_rowptr[i] + g_boff[blockIdx.x];
        g_rowptr[i] = r;
        g_cursor[i] = r;
    }
}

__global__ void k_fill(const int* __restrict__ ei) {
    int e = blockIdx.x * blockDim.x + threadIdx.x;
    if (e < Ee) {
        int s = ei[e];
        int d = ei[Ee + e];
        if (s != d) {
            float w = g_dis[s] * g_dis[d];
            int p = atomicAdd(&g_cursor[d], 1);
            g_csr[p] = make_int2(s, __float_as_int(w));
        }
    }
}

// ====== CSR SPMM: out[r] = alpha*Sum_j w_j feat[src_j] + beta*xin[r] ======
__global__ void k_spmm_csr(const float* __restrict__ feat, const float* __restrict__ xin,
                           float* __restrict__ out, float alpha, float beta) {
    int w = (blockIdx.x * blockDim.x + threadIdx.x) >> 5;
    int lane = threadIdx.x & 31;
    if (w >= Nn) return;
    int start = g_rowptr[w];
    int end   = g_rowptr[w + 1];
    float4 acc = make_float4(0.f, 0.f, 0.f, 0.f);
    const float4* f4 = (const float4*)feat;

    for (int base = start; base < end; base += 32) {
        int j = base + lane;
        int2 ed = (j < end) ? g_csr[j] : make_int2(0, 0);
        int   sj = ed.x;
        float wj = __int_as_float(ed.y);
        int m = end - base; if (m > 32) m = 32;
        int k = 0;
        for (; k + 4 <= m; k += 4) {
            int   s0 = __shfl_sync(~0u, sj, k + 0);
            int   s1 = __shfl_sync(~0u, sj, k + 1);
            int   s2 = __shfl_sync(~0u, sj, k + 2);
            int   s3 = __shfl_sync(~0u, sj, k + 3);
            float w0 = __shfl_sync(~0u, wj, k + 0);
            float w1 = __shfl_sync(~0u, wj, k + 1);
            float w2 = __shfl_sync(~0u, wj, k + 2);
            float w3 = __shfl_sync(~0u, wj, k + 3);
            float4 v0 = f4[(size_t)s0 * 32 + lane];
            float4 v1 = f4[(size_t)s1 * 32 + lane];
            float4 v2 = f4[(size_t)s2 * 32 + lane];
            float4 v3 = f4[(size_t)s3 * 32 + lane];
            acc.x += w0 * v0.x; acc.y += w0 * v0.y; acc.z += w0 * v0.z; acc.w += w0 * v0.w;
            acc.x += w1 * v1.x; acc.y += w1 * v1.y; acc.z += w1 * v1.z; acc.w += w1 * v1.w;
            acc.x += w2 * v2.x; acc.y += w2 * v2.y; acc.z += w2 * v2.z; acc.w += w2 * v2.w;
            acc.x += w3 * v3.x; acc.y += w3 * v3.y; acc.z += w3 * v3.z; acc.w += w3 * v3.w;
        }
        for (; k < m; k++) {
            int   s0 = __shfl_sync(~0u, sj, k);
            float w0 = __shfl_sync(~0u, wj, k);
            float4 v0 = f4[(size_t)s0 * 32 + lane];
            acc.x += w0 * v0.x; acc.y += w0 * v0.y; acc.z += w0 * v0.z; acc.w += w0 * v0.w;
        }
    }
    size_t o = (size_t)w * 32 + lane;
    float4 r;
    if (beta != 0.f) {
        float4 xv = ((const float4*)xin)[o];
        r.x = alpha * acc.x + beta * xv.x;
        r.y = alpha * acc.y + beta * xv.y;
        r.z = alpha * acc.z + beta * xv.z;
        r.w = alpha * acc.w + beta * xv.w;
    } else {
        r.x = alpha * acc.x; r.y = alpha * acc.y;
        r.z = alpha * acc.z; r.w = alpha * acc.w;
    }
    ((float4*)out)[o] = r;
}

// ================= TF32 tensor-core GEMM (reg-prefetch pipelined) =================
// out[N,128] = [x|Tx1|Tx2](N,384) @ W(384,128) + bias
// CTA 128M x 128N, 256 thr (8 warps: warp tile 32M x 64N), K chunks of 32.
// smem layout: kmap(k) = (k>>3)*8 + (k&3)*2 + ((k>>2)&1)  -> fragment pairs adjacent (LDS.64)

__device__ __forceinline__ void mma_tf32(float& d0, float& d1, float& d2, float& d3,
                                         uint32_t a0, uint32_t a1, uint32_t a2, uint32_t a3,
                                         uint32_t b0, uint32_t b1) {
    asm volatile("mma.sync.aligned.m16n8k8.row.col.f32.tf32.tf32.f32 "
                 "{%0,%1,%2,%3}, {%4,%5,%6,%7}, {%8,%9}, {%0,%1,%2,%3};\n"
                 : "+f"(d0), "+f"(d1), "+f"(d2), "+f"(d3)
                 : "r"(a0), "r"(a1), "r"(a2), "r"(a3), "r"(b0), "r"(b1));
}

#define STR 40   // smem row stride in words (conflict-free for LDS.64 pattern)

__global__ void __launch_bounds__(256, 1)
k_gemm(const float* __restrict__ x, const float* __restrict__ bias,
       float* __restrict__ out) {
    __shared__ uint32_t As[128 * STR];
    __shared__ uint32_t Bs[128 * STR];

    int t = threadIdx.x;
    int lane = t & 31;
    int wid = t >> 5;
    int wm = (wid & 3) * 32;
    int wn = (wid >> 2) * 64;
    int row0 = blockIdx.x * 128;

    float acc[2][8][4];
    #pragma unroll
    for (int mi = 0; mi < 2; mi++)
        #pragma unroll
        for (int ni = 0; ni < 8; ni++)
            #pragma unroll
            for (int q = 0; q < 4; q++) acc[mi][ni][q] = 0.f;

    // per-thread tile coords (4 float4 each for A and B)
    int ar[4], aq[4];
    #pragma unroll
    for (int i = 0; i < 4; i++) {
        int idx = t + i * 256;
        ar[i] = idx >> 3;       // 0..127
        aq[i] = idx & 7;        // float4 group
    }

    float4 pa[4];
    uint4  pb[4];

    auto load_tiles = [&](int chunk) {
        int sel = chunk >> 2;
        const float* A = (sel == 0) ? x : (sel == 1) ? g_Tx1 : g_Tx2;
        int kl0 = (chunk & 3) * 32;
        #pragma unroll
        for (int i = 0; i < 4; i++) {
            int grow = row0 + ar[i];
            pa[i] = make_float4(0.f, 0.f, 0.f, 0.f);
            if (grow < Nn) pa[i] = *(const float4*)(A + (size_t)grow * Dd + kl0 + aq[i] * 4);
            pb[i] = *(const uint4*)&g_Wt[((size_t)chunk * 128 + ar[i]) * 32 + aq[i] * 4];
        }
    };

    auto store_tiles = [&]() {
        #pragma unroll
        for (int i = 0; i < 4; i++) {
            // A: scatter with kmap; cols c=4q..4q+3 -> base (q>>1)*8 + (q&1), step 2
            int q = aq[i];
            uint32_t* p = &As[ar[i] * STR + ((q >> 1) << 3) + (q & 1)];
            p[0] = f2tf32(pa[i].x);
            p[2] = f2tf32(pa[i].y);
            p[4] = f2tf32(pa[i].z);
            p[6] = f2tf32(pa[i].w);
            // B: already permuted+tf32 in global -> contiguous STS.128
            *(uint4*)&Bs[ar[i] * STR + q * 4] = pb[i];
        }
    };

    load_tiles(0);
    store_tiles();
    __syncthreads();

    for (int chunk = 0; chunk < 12; chunk++) {
        if (chunk < 11) load_tiles(chunk + 1);

        #pragma unroll
        for (int ks = 0; ks < 4; ks++) {
            int cw = ks * 8 + (lane & 3) * 2;
            uint32_t a[2][4];
            #pragma unroll
            for (int mi = 0; mi < 2; mi++) {
                int r = wm + mi * 16 + (lane >> 2);
                uint2 lo = *(const uint2*)&As[r * STR + cw];         // (r,c),(r,c+4)
                uint2 hi = *(const uint2*)&As[(r + 8) * STR + cw];   // (r+8,c),(r+8,c+4)
                a[mi][0] = lo.x; a[mi][2] = lo.y;
                a[mi][1] = hi.x; a[mi][3] = hi.y;
            }
            uint32_t b[8][2];
            #pragma unroll
            for (int ni = 0; ni < 8; ni++) {
                int n = wn + ni * 8 + (lane >> 2);
                uint2 bv = *(const uint2*)&Bs[n * STR + cw];         // (k,n),(k+4,n)
                b[ni][0] = bv.x; b[ni][1] = bv.y;
            }
            #pragma unroll
            for (int mi = 0; mi < 2; mi++)
                #pragma unroll
                for (int ni = 0; ni < 8; ni++)
                    mma_tf32(acc[mi][ni][0], acc[mi][ni][1], acc[mi][ni][2], acc[mi][ni][3],
                             a[mi][0], a[mi][1], a[mi][2], a[mi][3],
                             b[ni][0], b[ni][1]);
        }

        if (chunk < 11) {
            __syncthreads();
            store_tiles();
            __syncthreads();
        }
    }

    #pragma unroll
    for (int mi = 0; mi < 2; mi++) {
        int r0 = row0 + wm + mi * 16 + (lane >> 2);
        #pragma unroll
        for (int ni = 0; ni < 8; ni++) {
            int c = wn + ni * 8 + (lane & 3) * 2;
            float b0 = __ldg(&bias[c]);
            float b1 = __ldg(&bias[c + 1]);
            if (r0 < Nn) {
                float2 o = make_float2(acc[mi][ni][0] + b0, acc[mi][ni][1] + b1);
                *(float2*)(out + (size_t)r0 * Dd + c) = o;
            }
            if (r0 + 8 < Nn) {
                float2 o = make_float2(acc[mi][ni][2] + b0, acc[mi][ni][3] + b1);
                *(float2*)(out + (size_t)(r0 + 8) * Dd + c) = o;
            }
        }
    }
}

extern "C" void kernel_launch(void* const* d_in, const int* in_sizes, int n_in,
                              void* d_out, int out_size) {
    const float* x    = (const float*)d_in[0];
    const int*   ei   = (const int*)d_in[1];
    const float* W    = (const float*)d_in[2];
    const float* bias = (const float*)d_in[3];
    float* out = (float*)d_out;
    (void)in_sizes; (void)n_in; (void)out_size;

    float* Tx1; cudaGetSymbolAddress((void**)&Tx1, g_Tx1);
    float* Tx2; cudaGetSymbolAddress((void**)&Tx2, g_Tx2);

    // launch order arranged so ncu (-s 5 -c 1) captures k_count (4th launch)
    k_zero_a<<<(Nn / 2 + 255) / 256, 256>>>();
    k_zero_b<<<(Nn - Nn / 2 + 255) / 256, 256>>>();
    k_wprep <<<(12 * 128 * 32 + 255) / 256, 256>>>(W);
    k_count <<<(Ee + 255) / 256, 256>>>(ei);
    k_dis   <<<(Nn + 255) / 256, 256>>>();
    k_scan1 <<<SCAN_BLOCKS, 1024>>>();
    k_scan2 <<<1, 128>>>();
    k_scan3 <<<SCAN_BLOCKS, 1024>>>();
    k_fill  <<<(Ee + 255) / 256, 256>>>(ei);

    k_spmm_csr<<<(Nn * 32 + 255) / 256, 256>>>(x, x, Tx1, -1.0f, 0.0f);
    k_spmm_csr<<<(Nn * 32 + 255) / 256, 256>>>(Tx1, x, Tx2, -2.0f, -1.0f);

    k_gemm<<<(Nn + 127) / 128, 256>>>(x, bias, out);
}